// round 12
// baseline (speedup 1.0000x reference)
#include <cuda_runtime.h>
#include <cuda_bf16.h>
#include <cstdint>

#define NPTS   50000
#define KNN    16
#define CH     128
#define CSH    16
#define MROWS  (NPTS*KNN)
#define BN_EPS 1e-5f
#define NBLK   592

// ---------------- device scratch (no allocations allowed) ----------------
__device__ __align__(16) float g_z[NPTS*CSH];
__device__ __align__(16) float g_num[NPTS*CSH];
__device__ float g_part[NBLK][6];            // per-block BN stat partials
__device__ __align__(16) float g_M[3*CSH];   // folded p-path matrix, logical cols
__device__ __align__(16) float g_Bc[CSH];    // folded s bias, logical cols
__device__ float g_wf[9];                    // BN-folded W_p1
__device__ float g_gb[3];                    // BN shift
// fragment-packed B: entry (ks,nt,lane) = 16B {bh0,bh1,bl0,bl1}
__device__ __align__(16) unsigned char g_Bpk[16384];

// logical n column of physical B row p (within a 16-block)
__host__ __device__ __forceinline__ int perm16(int q) {
    return ((q & 7) >> 1) * 4 + ((q >> 3) << 1) + (q & 1);
}

// ---------------- prep: B pack + BN stat partials + zero accumulators ----------------
__global__ void prep_kernel(const float* __restrict__ p_r,
                            const float* __restrict__ W_p1,
                            const float* __restrict__ W_lin,
                            const float* __restrict__ W_x) {
    int gid = blockIdx.x*blockDim.x + threadIdx.x;
    int stride = gridDim.x*blockDim.x;

    // --- B fragment packing (first 4096 threads) ---
    if (gid < 4096) {
        int ei = gid;
        int w    = ei & 3;            // 0:bh0 1:bh1 2:bl0 3:bl1
        int lane = (ei >> 2) & 31;
        int nt   = (ei >> 7) & 3;
        int ks   = ei >> 9;
        int t = lane & 3;
        int p = (lane >> 2) + 8*nt;                  // physical B row 0..31
        int l = perm16(p & 15);                      // logical output column
        int k0 = 16*ks + 4*t + (w & 1)*2;            // logical k of low bf16
        float v0 = (p < 16) ? W_lin[l*256 + 128 + k0]     : W_x[l*128 + k0];
        float v1 = (p < 16) ? W_lin[l*256 + 128 + k0 + 1] : W_x[l*128 + k0 + 1];
        __nv_bfloat162 out;
        if (w < 2) {
            out.x = __float2bfloat16_rn(v0);
            out.y = __float2bfloat16_rn(v1);
        } else {
            __nv_bfloat16 h0 = __float2bfloat16_rn(v0);
            __nv_bfloat16 h1 = __float2bfloat16_rn(v1);
            out.x = __float2bfloat16_rn(v0 - __bfloat162float(h0));
            out.y = __float2bfloat16_rn(v1 - __bfloat162float(h1));
        }
        reinterpret_cast<uint32_t*>(g_Bpk)[ei] = *reinterpret_cast<uint32_t*>(&out);
    }

    // --- zero z/num accumulators ---
    for (int i = gid; i < NPTS*CSH; i += stride) { g_z[i] = 0.f; g_num[i] = 0.f; }

    // --- BN stats over h = p_r @ W_p1^T ---
    float w0=W_p1[0],w1=W_p1[1],w2=W_p1[2],w3=W_p1[3],w4=W_p1[4],
          w5=W_p1[5],w6=W_p1[6],w7=W_p1[7],w8=W_p1[8];
    float s0=0,s1=0,s2=0,q0=0,q1=0,q2=0;
    for (int i = gid; i < MROWS; i += stride) {
        float p0=p_r[3*i+0], p1=p_r[3*i+1], p2=p_r[3*i+2];
        float h0 = p0*w0 + p1*w1 + p2*w2;
        float h1 = p0*w3 + p1*w4 + p2*w5;
        float h2 = p0*w6 + p1*w7 + p2*w8;
        s0+=h0; q0+=h0*h0; s1+=h1; q1+=h1*h1; s2+=h2; q2+=h2*h2;
    }
    #pragma unroll
    for (int o=16;o>0;o>>=1){
        s0+=__shfl_down_sync(0xffffffffu,s0,o);
        s1+=__shfl_down_sync(0xffffffffu,s1,o);
        s2+=__shfl_down_sync(0xffffffffu,s2,o);
        q0+=__shfl_down_sync(0xffffffffu,q0,o);
        q1+=__shfl_down_sync(0xffffffffu,q1,o);
        q2+=__shfl_down_sync(0xffffffffu,q2,o);
    }
    __shared__ float red[8][6];
    int wid = threadIdx.x>>5, lid = threadIdx.x&31;
    if (lid==0){ red[wid][0]=s0; red[wid][1]=s1; red[wid][2]=s2;
                 red[wid][3]=q0; red[wid][4]=q1; red[wid][5]=q2; }
    __syncthreads();
    if (threadIdx.x < 6) {
        float a = 0.f;
        #pragma unroll
        for (int w=0; w<8; w++) a += red[w][threadIdx.x];
        g_part[blockIdx.x][threadIdx.x] = a;
    }
}

// ---------------- fold constants (parallel: 5 blocks x 512) ----------------
__global__ void consts_kernel(const float* __restrict__ W_lin,
                              const float* __restrict__ b_lin,
                              const float* __restrict__ W_p2,
                              const float* __restrict__ b_p2,
                              const float* __restrict__ W_p1,
                              const float* __restrict__ gamma,
                              const float* __restrict__ beta) {
    int tid  = threadIdx.x;
    int wid  = tid >> 5;
    int lane = tid & 31;

    if (blockIdx.x == 4) {
        // BN-stat reduce + fold
        __shared__ float st[6];
        if (tid < 192) {
            int c = tid >> 5;
            float a = 0.f;
            for (int j = lane; j < NBLK; j += 32) a += g_part[j][c];
            #pragma unroll
            for (int o=16;o>0;o>>=1) a += __shfl_down_sync(0xffffffffu, a, o);
            if (lane == 0) st[c] = a;
        }
        __syncthreads();
        if (tid < 3) {
            float inv = 1.f / (float)MROWS;
            float mu  = st[tid] * inv;
            float var = st[3+tid] * inv - mu*mu;
            float gs  = gamma[tid] * rsqrtf(var + BN_EPS);
            g_gb[tid] = beta[tid] - mu*gs;
            #pragma unroll
            for (int c=0;c<3;c++) g_wf[tid*3+c] = gs * W_p1[tid*3+c];
        }
        return;
    }

    // warp-per-output dot products: gw 0..47 -> g_M, 48..63 -> g_Bc
    int gw = blockIdx.x * 16 + wid;
    if (gw < 48) {
        int a = gw >> 4, j = gw & 15;
        float m = 0.f;
        for (int c = lane; c < CH; c += 32) m += W_p2[c*3+a] * W_lin[j*256+c];
        #pragma unroll
        for (int o=16;o>0;o>>=1) m += __shfl_down_sync(0xffffffffu, m, o);
        if (lane == 0) g_M[a*CSH + j] = m;
    } else {
        int j = gw - 48;
        float b = 0.f;
        for (int c = lane; c < CH; c += 32) b += b_p2[c] * W_lin[j*256+c];
        #pragma unroll
        for (int o=16;o>0;o>>=1) b += __shfl_down_sync(0xffffffffu, b, o);
        if (lane == 0) g_Bc[j] = b + b_lin[j];
    }
}

#define SMEM_DYN 16384

__device__ __forceinline__ void mma16816(float* c, const uint32_t* a,
                                         uint32_t b0, uint32_t b1) {
    asm volatile("mma.sync.aligned.m16n8k16.row.col.f32.bf16.bf16.f32 "
                 "{%0,%1,%2,%3}, {%4,%5,%6,%7}, {%8,%9}, {%0,%1,%2,%3};"
                 : "+f"(c[0]), "+f"(c[1]), "+f"(c[2]), "+f"(c[3])
                 : "r"(a[0]), "r"(a[1]), "r"(a[2]), "r"(a[3]), "r"(b0), "r"(b1));
}

// fp32 pair -> bf16x2 hi + bf16x2 lo
__device__ __forceinline__ void cvt2(float x, float y, uint32_t& h, uint32_t& l) {
    float2 f; f.x = x; f.y = y;
    __nv_bfloat162 hh = __float22bfloat162_rn(f);
    float2 r;
    r.x = f.x - __bfloat162float(hh.x);
    r.y = f.y - __bfloat162float(hh.y);
    __nv_bfloat162 ll = __float22bfloat162_rn(r);
    h = *reinterpret_cast<uint32_t*>(&hh);
    l = *reinterpret_cast<uint32_t*>(&ll);
}

// ---------------- fused main kernel (R9/R11 proven config) ----------------
__global__ void __launch_bounds__(128, 4) main_kernel(
    const float* __restrict__ x_knn,
    const int*   __restrict__ knn_idx,
    const float* __restrict__ p_r,
    const float* __restrict__ b_x)
{
    extern __shared__ char smp[];

    const int tid  = threadIdx.x;
    const int lane = tid & 31;
    const int wid  = tid >> 5;
    const int base = blockIdx.x * 128;

    // ---- stage B once: raw copy of fragment-packed data (16384B) ----
    {
        const uint4* bs = reinterpret_cast<const uint4*>(g_Bpk);
        #pragma unroll
        for (int i = 0; i < 8; i++)
            *reinterpret_cast<uint4*>(smp + (i*128 + tid)*16) = bs[i*128 + tid];
    }
    __syncthreads();

    // ---- accumulators ----
    const int warp_row = wid * 32;
    float acc[2][4][4];   // [m-tile][n-tile: 0,1 s / 2,3 v][reg]
    #pragma unroll
    for (int m=0;m<2;m++)
        #pragma unroll
        for (int n=0;n<4;n++)
            #pragma unroll
            for (int r=0;r<4;r++) acc[m][n][r] = 0.f;

    // A base: row = base+warp_row+(lane>>2); 4 contiguous logical cols at 4*(lane&3)
    const float* A0 = x_knn + (size_t)(base + warp_row + (lane >> 2)) * 128 + (lane & 3) * 4;
    const uint32_t bLane = (uint32_t)lane * 16;

    #pragma unroll
    for (int ks = 0; ks < 8; ks++) {
        const int k0 = ks * 16;
        float4 fa[2], fb[2];
        #pragma unroll
        for (int mt = 0; mt < 2; mt++) {
            const float* p = A0 + mt*2048 + k0;
            fa[mt] = *reinterpret_cast<const float4*>(p);          // rows 0-7 of tile
            fb[mt] = *reinterpret_cast<const float4*>(p + 1024);   // rows 8-15
        }
        uint32_t ah[2][4], al[2][4];
        #pragma unroll
        for (int mt = 0; mt < 2; mt++) {
            cvt2(fa[mt].x, fa[mt].y, ah[mt][0], al[mt][0]);
            cvt2(fb[mt].x, fb[mt].y, ah[mt][1], al[mt][1]);
            cvt2(fa[mt].z, fa[mt].w, ah[mt][2], al[mt][2]);
            cvt2(fb[mt].z, fb[mt].w, ah[mt][3], al[mt][3]);
        }

        #pragma unroll
        for (int nt = 0; nt < 4; nt++) {
            uint4 bv = *reinterpret_cast<const uint4*>(
                smp + ((ks*4 + nt) << 9) + bLane);
            mma16816(acc[0][nt], ah[0], bv.x, bv.y);
            mma16816(acc[1][nt], ah[1], bv.x, bv.y);
            mma16816(acc[0][nt], al[0], bv.x, bv.y);
            mma16816(acc[1][nt], al[1], bv.x, bv.y);
            mma16816(acc[0][nt], ah[0], bv.z, bv.w);
            mma16816(acc[1][nt], ah[1], bv.z, bv.w);
        }
    }

    // ---- epilogue: logical cols 4t..4t+3 contiguous -> red.v4 ----
    const int t  = lane & 3;
    const int l4 = lane >> 2;
    float4 Bc4 = *reinterpret_cast<const float4*>(&g_Bc[4*t]);
    float4 bx4 = *reinterpret_cast<const float4*>(&b_x[4*t]);
    float4 M0  = *reinterpret_cast<const float4*>(&g_M[4*t]);
    float4 M1  = *reinterpret_cast<const float4*>(&g_M[16 + 4*t]);
    float4 M2  = *reinterpret_cast<const float4*>(&g_M[32 + 4*t]);
    float wf0=g_wf[0],wf1=g_wf[1],wf2=g_wf[2],wf3=g_wf[3],wf4=g_wf[4],
          wf5=g_wf[5],wf6=g_wf[6],wf7=g_wf[7],wf8=g_wf[8];
    float gb0=g_gb[0],gb1=g_gb[1],gb2=g_gb[2];

    #pragma unroll
    for (int mt = 0; mt < 2; mt++) {
        #pragma unroll
        for (int hh = 0; hh < 2; hh++) {
            int row = base + warp_row + 16*mt + 8*hh + l4;
            float p0 = p_r[3*row+0], p1 = p_r[3*row+1], p2 = p_r[3*row+2];
            float hv0 = fmaxf(p0*wf0 + p1*wf1 + p2*wf2 + gb0, 0.f);
            float hv1 = fmaxf(p0*wf3 + p1*wf4 + p2*wf5 + gb1, 0.f);
            float hv2 = fmaxf(p0*wf6 + p1*wf7 + p2*wf8 + gb2, 0.f);
            int idx = knn_idx[row];
            float e0 = __expf(fmaxf(acc[mt][0][2*hh+0] + Bc4.x + hv0*M0.x + hv1*M1.x + hv2*M2.x, 0.f));
            float e1 = __expf(fmaxf(acc[mt][0][2*hh+1] + Bc4.y + hv0*M0.y + hv1*M1.y + hv2*M2.y, 0.f));
            float e2 = __expf(fmaxf(acc[mt][1][2*hh+0] + Bc4.z + hv0*M0.z + hv1*M1.z + hv2*M2.z, 0.f));
            float e3 = __expf(fmaxf(acc[mt][1][2*hh+1] + Bc4.w + hv0*M0.w + hv1*M1.w + hv2*M2.w, 0.f));
            float w0 = fmaxf(acc[mt][2][2*hh+0] + bx4.x, 0.f) * e0;
            float w1 = fmaxf(acc[mt][2][2*hh+1] + bx4.y, 0.f) * e1;
            float w2 = fmaxf(acc[mt][3][2*hh+0] + bx4.z, 0.f) * e2;
            float w3 = fmaxf(acc[mt][3][2*hh+1] + bx4.w, 0.f) * e3;
            float* zp = &g_z[idx*CSH + 4*t];
            float* np = &g_num[idx*CSH + 4*t];
            asm volatile("red.global.add.v4.f32 [%0], {%1,%2,%3,%4};"
                         :: "l"(zp), "f"(e0), "f"(e1), "f"(e2), "f"(e3) : "memory");
            asm volatile("red.global.add.v4.f32 [%0], {%1,%2,%3,%4};"
                         :: "l"(np), "f"(w0), "f"(w1), "f"(w2), "f"(w3) : "memory");
        }
    }
}

// ---------------- output: warp-cooperative x + tile(num/z, 8) ----------------
// grid*block == NPTS*32 exactly; each warp covers one point n.
__global__ void out_kernel(const float* __restrict__ x, float* __restrict__ out) {
    int i = blockIdx.x*blockDim.x + threadIdx.x;   // exact fit: no stragglers
    int n = i >> 5, q = i & 31;

    // lanes 0..3 compute the 4-wide ratio for jb = 4*lane; others get it via shfl
    float4 r;
    if (q < 4) {
        float4 zv = *reinterpret_cast<const float4*>(&g_z[n*CSH + q*4]);
        float4 nv = *reinterpret_cast<const float4*>(&g_num[n*CSH + q*4]);
        r.x = zv.x > 0.f ? nv.x / zv.x : 0.f;
        r.y = zv.y > 0.f ? nv.y / zv.y : 0.f;
        r.z = zv.z > 0.f ? nv.z / zv.z : 0.f;
        r.w = zv.w > 0.f ? nv.w / zv.w : 0.f;
    }
    int src = q & 3;
    r.x = __shfl_sync(0xffffffffu, r.x, src);
    r.y = __shfl_sync(0xffffffffu, r.y, src);
    r.z = __shfl_sync(0xffffffffu, r.z, src);
    r.w = __shfl_sync(0xffffffffu, r.w, src);

    float4 xv = reinterpret_cast<const float4*>(x)[i];
    float4 o;
    o.x = xv.x + r.x;
    o.y = xv.y + r.y;
    o.z = xv.z + r.z;
    o.w = xv.w + r.w;
    reinterpret_cast<float4*>(out)[i] = o;
}

// ---------------- launch ----------------
extern "C" void kernel_launch(void* const* d_in, const int* in_sizes, int n_in,
                              void* d_out, int out_size) {
    (void)in_sizes; (void)n_in; (void)out_size;
    const float* x       = (const float*)d_in[0];
    const float* x_knn   = (const float*)d_in[1];
    const int*   knn_idx = (const int*)  d_in[2];
    const float* p_r     = (const float*)d_in[3];
    const float* W_lin   = (const float*)d_in[4];
    const float* b_lin   = (const float*)d_in[5];
    const float* W_x     = (const float*)d_in[6];
    const float* b_x     = (const float*)d_in[7];
    const float* W_p1    = (const float*)d_in[8];
    const float* gamma   = (const float*)d_in[9];
    const float* beta    = (const float*)d_in[10];
    const float* W_p2    = (const float*)d_in[11];
    const float* b_p2    = (const float*)d_in[12];

    cudaFuncSetAttribute(main_kernel, cudaFuncAttributeMaxDynamicSharedMemorySize, SMEM_DYN);

    prep_kernel<<<NBLK, 256>>>(p_r, W_p1, W_lin, W_x);
    consts_kernel<<<5, 512>>>(W_lin, b_lin, W_p2, b_p2, W_p1, gamma, beta);
    main_kernel<<<MROWS/128, 128, SMEM_DYN>>>(x_knn, knn_idx, p_r, b_x);
    out_kernel<<<(NPTS*32)/256, 256>>>(x, (float*)d_out);
}

// round 13
// speedup vs baseline: 1.0246x; 1.0246x over previous
#include <cuda_runtime.h>
#include <cuda_bf16.h>
#include <cstdint>

#define NPTS   50000
#define KNN    16
#define CH     128
#define CSH    16
#define MROWS  (NPTS*KNN)
#define BN_EPS 1e-5f
#define NBLK   592

// ---------------- device scratch (no allocations allowed) ----------------
__device__ __align__(16) float g_z[NPTS*CSH];
__device__ __align__(16) float g_num[NPTS*CSH];
__device__ float g_part[NBLK][6];            // per-block BN stat partials
__device__ __align__(16) float g_M[3*CSH];   // folded p-path matrix, logical cols
__device__ __align__(16) float g_Bc[CSH];    // folded s bias, logical cols
__device__ float g_wf[9];                    // BN-folded W_p1
__device__ float g_gb[3];                    // BN shift
// fragment-packed B: entry (ks,nt,lane) = 16B {bh0,bh1,bl0,bl1}
__device__ __align__(16) unsigned char g_Bpk[16384];

// logical n column of physical B row p (within a 16-block)
__host__ __device__ __forceinline__ int perm16(int q) {
    return ((q & 7) >> 1) * 4 + ((q >> 3) << 1) + (q & 1);
}

// ---------------- prep: B pack + BN stat partials + zero accumulators ----------------
__global__ void prep_kernel(const float* __restrict__ p_r,
                            const float* __restrict__ W_p1,
                            const float* __restrict__ W_lin,
                            const float* __restrict__ W_x) {
    int gid = blockIdx.x*blockDim.x + threadIdx.x;
    int stride = gridDim.x*blockDim.x;

    // --- B fragment packing (first 4096 threads) ---
    if (gid < 4096) {
        int ei = gid;
        int w    = ei & 3;            // 0:bh0 1:bh1 2:bl0 3:bl1
        int lane = (ei >> 2) & 31;
        int nt   = (ei >> 7) & 3;
        int ks   = ei >> 9;
        int t = lane & 3;
        int p = (lane >> 2) + 8*nt;                  // physical B row 0..31
        int l = perm16(p & 15);                      // logical output column
        int k0 = 16*ks + 4*t + (w & 1)*2;            // logical k of low bf16
        float v0 = (p < 16) ? W_lin[l*256 + 128 + k0]     : W_x[l*128 + k0];
        float v1 = (p < 16) ? W_lin[l*256 + 128 + k0 + 1] : W_x[l*128 + k0 + 1];
        __nv_bfloat162 out;
        if (w < 2) {
            out.x = __float2bfloat16_rn(v0);
            out.y = __float2bfloat16_rn(v1);
        } else {
            __nv_bfloat16 h0 = __float2bfloat16_rn(v0);
            __nv_bfloat16 h1 = __float2bfloat16_rn(v1);
            out.x = __float2bfloat16_rn(v0 - __bfloat162float(h0));
            out.y = __float2bfloat16_rn(v1 - __bfloat162float(h1));
        }
        reinterpret_cast<uint32_t*>(g_Bpk)[ei] = *reinterpret_cast<uint32_t*>(&out);
    }

    // --- zero z/num accumulators ---
    for (int i = gid; i < NPTS*CSH; i += stride) { g_z[i] = 0.f; g_num[i] = 0.f; }

    // --- BN stats over h = p_r @ W_p1^T ---
    float w0=W_p1[0],w1=W_p1[1],w2=W_p1[2],w3=W_p1[3],w4=W_p1[4],
          w5=W_p1[5],w6=W_p1[6],w7=W_p1[7],w8=W_p1[8];
    float s0=0,s1=0,s2=0,q0=0,q1=0,q2=0;
    for (int i = gid; i < MROWS; i += stride) {
        float p0=p_r[3*i+0], p1=p_r[3*i+1], p2=p_r[3*i+2];
        float h0 = p0*w0 + p1*w1 + p2*w2;
        float h1 = p0*w3 + p1*w4 + p2*w5;
        float h2 = p0*w6 + p1*w7 + p2*w8;
        s0+=h0; q0+=h0*h0; s1+=h1; q1+=h1*h1; s2+=h2; q2+=h2*h2;
    }
    #pragma unroll
    for (int o=16;o>0;o>>=1){
        s0+=__shfl_down_sync(0xffffffffu,s0,o);
        s1+=__shfl_down_sync(0xffffffffu,s1,o);
        s2+=__shfl_down_sync(0xffffffffu,s2,o);
        q0+=__shfl_down_sync(0xffffffffu,q0,o);
        q1+=__shfl_down_sync(0xffffffffu,q1,o);
        q2+=__shfl_down_sync(0xffffffffu,q2,o);
    }
    __shared__ float red[8][6];
    int wid = threadIdx.x>>5, lid = threadIdx.x&31;
    if (lid==0){ red[wid][0]=s0; red[wid][1]=s1; red[wid][2]=s2;
                 red[wid][3]=q0; red[wid][4]=q1; red[wid][5]=q2; }
    __syncthreads();
    if (threadIdx.x < 6) {
        float a = 0.f;
        #pragma unroll
        for (int w=0; w<8; w++) a += red[w][threadIdx.x];
        g_part[blockIdx.x][threadIdx.x] = a;
    }
}

// ---------------- fold constants (parallel: 5 blocks x 512) ----------------
__global__ void consts_kernel(const float* __restrict__ W_lin,
                              const float* __restrict__ b_lin,
                              const float* __restrict__ W_p2,
                              const float* __restrict__ b_p2,
                              const float* __restrict__ W_p1,
                              const float* __restrict__ gamma,
                              const float* __restrict__ beta) {
    int tid  = threadIdx.x;
    int wid  = tid >> 5;
    int lane = tid & 31;

    if (blockIdx.x == 4) {
        // BN-stat reduce + fold
        __shared__ float st[6];
        if (tid < 192) {
            int c = tid >> 5;
            float a = 0.f;
            for (int j = lane; j < NBLK; j += 32) a += g_part[j][c];
            #pragma unroll
            for (int o=16;o>0;o>>=1) a += __shfl_down_sync(0xffffffffu, a, o);
            if (lane == 0) st[c] = a;
        }
        __syncthreads();
        if (tid < 3) {
            float inv = 1.f / (float)MROWS;
            float mu  = st[tid] * inv;
            float var = st[3+tid] * inv - mu*mu;
            float gs  = gamma[tid] * rsqrtf(var + BN_EPS);
            g_gb[tid] = beta[tid] - mu*gs;
            #pragma unroll
            for (int c=0;c<3;c++) g_wf[tid*3+c] = gs * W_p1[tid*3+c];
        }
        return;
    }

    // warp-per-output dot products: gw 0..47 -> g_M, 48..63 -> g_Bc
    int gw = blockIdx.x * 16 + wid;
    if (gw < 48) {
        int a = gw >> 4, j = gw & 15;
        float m = 0.f;
        for (int c = lane; c < CH; c += 32) m += W_p2[c*3+a] * W_lin[j*256+c];
        #pragma unroll
        for (int o=16;o>0;o>>=1) m += __shfl_down_sync(0xffffffffu, m, o);
        if (lane == 0) g_M[a*CSH + j] = m;
    } else {
        int j = gw - 48;
        float b = 0.f;
        for (int c = lane; c < CH; c += 32) b += b_p2[c] * W_lin[j*256+c];
        #pragma unroll
        for (int o=16;o>0;o>>=1) b += __shfl_down_sync(0xffffffffu, b, o);
        if (lane == 0) g_Bc[j] = b + b_lin[j];
    }
}

#define SMEM_DYN 16384

__device__ __forceinline__ void mma16816(float* c, const uint32_t* a,
                                         uint32_t b0, uint32_t b1) {
    asm volatile("mma.sync.aligned.m16n8k16.row.col.f32.bf16.bf16.f32 "
                 "{%0,%1,%2,%3}, {%4,%5,%6,%7}, {%8,%9}, {%0,%1,%2,%3};"
                 : "+f"(c[0]), "+f"(c[1]), "+f"(c[2]), "+f"(c[3])
                 : "r"(a[0]), "r"(a[1]), "r"(a[2]), "r"(a[3]), "r"(b0), "r"(b1));
}

// fp32 pair -> bf16x2 hi + bf16x2 lo
__device__ __forceinline__ void cvt2(float x, float y, uint32_t& h, uint32_t& l) {
    float2 f; f.x = x; f.y = y;
    __nv_bfloat162 hh = __float22bfloat162_rn(f);
    float2 r;
    r.x = f.x - __bfloat162float(hh.x);
    r.y = f.y - __bfloat162float(hh.y);
    __nv_bfloat162 ll = __float22bfloat162_rn(r);
    h = *reinterpret_cast<uint32_t*>(&hh);
    l = *reinterpret_cast<uint32_t*>(&ll);
}

// ---------------- fused main kernel (R9/R11 proven config) ----------------
__global__ void __launch_bounds__(128, 4) main_kernel(
    const float* __restrict__ x_knn,
    const int*   __restrict__ knn_idx,
    const float* __restrict__ p_r,
    const float* __restrict__ b_x)
{
    extern __shared__ char smp[];

    const int tid  = threadIdx.x;
    const int lane = tid & 31;
    const int wid  = tid >> 5;
    const int base = blockIdx.x * 128;

    // ---- stage B once: raw copy of fragment-packed data (16384B) ----
    {
        const uint4* bs = reinterpret_cast<const uint4*>(g_Bpk);
        #pragma unroll
        for (int i = 0; i < 8; i++)
            *reinterpret_cast<uint4*>(smp + (i*128 + tid)*16) = bs[i*128 + tid];
    }
    __syncthreads();

    // ---- accumulators ----
    const int warp_row = wid * 32;
    float acc[2][4][4];   // [m-tile][n-tile: 0,1 s / 2,3 v][reg]
    #pragma unroll
    for (int m=0;m<2;m++)
        #pragma unroll
        for (int n=0;n<4;n++)
            #pragma unroll
            for (int r=0;r<4;r++) acc[m][n][r] = 0.f;

    // A base: row = base+warp_row+(lane>>2); 4 contiguous logical cols at 4*(lane&3)
    const float* A0 = x_knn + (size_t)(base + warp_row + (lane >> 2)) * 128 + (lane & 3) * 4;
    const uint32_t bLane = (uint32_t)lane * 16;

    #pragma unroll
    for (int ks = 0; ks < 8; ks++) {
        const int k0 = ks * 16;
        float4 fa[2], fb[2];
        #pragma unroll
        for (int mt = 0; mt < 2; mt++) {
            const float* p = A0 + mt*2048 + k0;
            fa[mt] = *reinterpret_cast<const float4*>(p);          // rows 0-7 of tile
            fb[mt] = *reinterpret_cast<const float4*>(p + 1024);   // rows 8-15
        }
        uint32_t ah[2][4], al[2][4];
        #pragma unroll
        for (int mt = 0; mt < 2; mt++) {
            cvt2(fa[mt].x, fa[mt].y, ah[mt][0], al[mt][0]);
            cvt2(fb[mt].x, fb[mt].y, ah[mt][1], al[mt][1]);
            cvt2(fa[mt].z, fa[mt].w, ah[mt][2], al[mt][2]);
            cvt2(fb[mt].z, fb[mt].w, ah[mt][3], al[mt][3]);
        }

        #pragma unroll
        for (int nt = 0; nt < 4; nt++) {
            uint4 bv = *reinterpret_cast<const uint4*>(
                smp + ((ks*4 + nt) << 9) + bLane);
            mma16816(acc[0][nt], ah[0], bv.x, bv.y);
            mma16816(acc[1][nt], ah[1], bv.x, bv.y);
            mma16816(acc[0][nt], al[0], bv.x, bv.y);
            mma16816(acc[1][nt], al[1], bv.x, bv.y);
            mma16816(acc[0][nt], ah[0], bv.z, bv.w);
            mma16816(acc[1][nt], ah[1], bv.z, bv.w);
        }
    }

    // ---- epilogue: logical cols 4t..4t+3 contiguous -> red.v4 ----
    const int t  = lane & 3;
    const int l4 = lane >> 2;
    float4 Bc4 = *reinterpret_cast<const float4*>(&g_Bc[4*t]);
    float4 bx4 = *reinterpret_cast<const float4*>(&b_x[4*t]);
    float4 M0  = *reinterpret_cast<const float4*>(&g_M[4*t]);
    float4 M1  = *reinterpret_cast<const float4*>(&g_M[16 + 4*t]);
    float4 M2  = *reinterpret_cast<const float4*>(&g_M[32 + 4*t]);
    float wf0=g_wf[0],wf1=g_wf[1],wf2=g_wf[2],wf3=g_wf[3],wf4=g_wf[4],
          wf5=g_wf[5],wf6=g_wf[6],wf7=g_wf[7],wf8=g_wf[8];
    float gb0=g_gb[0],gb1=g_gb[1],gb2=g_gb[2];

    #pragma unroll
    for (int mt = 0; mt < 2; mt++) {
        #pragma unroll
        for (int hh = 0; hh < 2; hh++) {
            int row = base + warp_row + 16*mt + 8*hh + l4;
            float p0 = p_r[3*row+0], p1 = p_r[3*row+1], p2 = p_r[3*row+2];
            float hv0 = fmaxf(p0*wf0 + p1*wf1 + p2*wf2 + gb0, 0.f);
            float hv1 = fmaxf(p0*wf3 + p1*wf4 + p2*wf5 + gb1, 0.f);
            float hv2 = fmaxf(p0*wf6 + p1*wf7 + p2*wf8 + gb2, 0.f);
            int idx = knn_idx[row];
            float e0 = __expf(fmaxf(acc[mt][0][2*hh+0] + Bc4.x + hv0*M0.x + hv1*M1.x + hv2*M2.x, 0.f));
            float e1 = __expf(fmaxf(acc[mt][0][2*hh+1] + Bc4.y + hv0*M0.y + hv1*M1.y + hv2*M2.y, 0.f));
            float e2 = __expf(fmaxf(acc[mt][1][2*hh+0] + Bc4.z + hv0*M0.z + hv1*M1.z + hv2*M2.z, 0.f));
            float e3 = __expf(fmaxf(acc[mt][1][2*hh+1] + Bc4.w + hv0*M0.w + hv1*M1.w + hv2*M2.w, 0.f));
            float w0 = fmaxf(acc[mt][2][2*hh+0] + bx4.x, 0.f) * e0;
            float w1 = fmaxf(acc[mt][2][2*hh+1] + bx4.y, 0.f) * e1;
            float w2 = fmaxf(acc[mt][3][2*hh+0] + bx4.z, 0.f) * e2;
            float w3 = fmaxf(acc[mt][3][2*hh+1] + bx4.w, 0.f) * e3;
            float* zp = &g_z[idx*CSH + 4*t];
            float* np = &g_num[idx*CSH + 4*t];
            asm volatile("red.global.add.v4.f32 [%0], {%1,%2,%3,%4};"
                         :: "l"(zp), "f"(e0), "f"(e1), "f"(e2), "f"(e3) : "memory");
            asm volatile("red.global.add.v4.f32 [%0], {%1,%2,%3,%4};"
                         :: "l"(np), "f"(w0), "f"(w1), "f"(w2), "f"(w3) : "memory");
        }
    }
}

// ---------------- output: x + tile(num/z, 8), ILP x2 ----------------
#define OUT_HALF (NPTS*16)   // 800000 float4s per half

__device__ __forceinline__ float4 out_one(const float* __restrict__ x, int i) {
    int n = i >> 5, q = i & 31;
    int jb = (q & 3) * 4;
    float4 xv = reinterpret_cast<const float4*>(x)[i];
    float4 zv = *reinterpret_cast<const float4*>(&g_z[n*CSH + jb]);
    float4 nv = *reinterpret_cast<const float4*>(&g_num[n*CSH + jb]);
    float4 o;
    o.x = xv.x + (zv.x > 0.f ? __fdividef(nv.x, zv.x) : 0.f);
    o.y = xv.y + (zv.y > 0.f ? __fdividef(nv.y, zv.y) : 0.f);
    o.z = xv.z + (zv.z > 0.f ? __fdividef(nv.z, zv.z) : 0.f);
    o.w = xv.w + (zv.w > 0.f ? __fdividef(nv.w, zv.w) : 0.f);
    return o;
}

__global__ void out_kernel(const float* __restrict__ x, float* __restrict__ out) {
    int i0 = blockIdx.x*blockDim.x + threadIdx.x;   // 0..OUT_HALF-1 (exact fit)
    int i1 = i0 + OUT_HALF;
    float4 o0 = out_one(x, i0);
    float4 o1 = out_one(x, i1);
    reinterpret_cast<float4*>(out)[i0] = o0;
    reinterpret_cast<float4*>(out)[i1] = o1;
}

// ---------------- launch ----------------
extern "C" void kernel_launch(void* const* d_in, const int* in_sizes, int n_in,
                              void* d_out, int out_size) {
    (void)in_sizes; (void)n_in; (void)out_size;
    const float* x       = (const float*)d_in[0];
    const float* x_knn   = (const float*)d_in[1];
    const int*   knn_idx = (const int*)  d_in[2];
    const float* p_r     = (const float*)d_in[3];
    const float* W_lin   = (const float*)d_in[4];
    const float* b_lin   = (const float*)d_in[5];
    const float* W_x     = (const float*)d_in[6];
    const float* b_x     = (const float*)d_in[7];
    const float* W_p1    = (const float*)d_in[8];
    const float* gamma   = (const float*)d_in[9];
    const float* beta    = (const float*)d_in[10];
    const float* W_p2    = (const float*)d_in[11];
    const float* b_p2    = (const float*)d_in[12];

    cudaFuncSetAttribute(main_kernel, cudaFuncAttributeMaxDynamicSharedMemorySize, SMEM_DYN);

    prep_kernel<<<NBLK, 256>>>(p_r, W_p1, W_lin, W_x);
    consts_kernel<<<5, 512>>>(W_lin, b_lin, W_p2, b_p2, W_p1, gamma, beta);
    main_kernel<<<MROWS/128, 128, SMEM_DYN>>>(x_knn, knn_idx, p_r, b_x);
    out_kernel<<<OUT_HALF/256, 256>>>(x, (float*)d_out);
}